// round 1
// baseline (speedup 1.0000x reference)
#include <cuda_runtime.h>
#include <cuda_bf16.h>
#include <cstdint>

// StackLSTM: T=256 steps, B=64, H=1024, L=2 layers.
// gates[b][g*1024+j] = sum_k x[b][k]*W_ih[g*1024+j][k] + h[b][k]*W_hh[g*1024+j][k] + b_ih + b_hh
// Round 1 strategy: graph of 512 fused GEMM+cell kernels, fp32 math via packed
// fma.rn.f32x2 (FFMA2). h double-buffered by timestep parity; c updated in place
// (each (b,j) owned by exactly one thread per layer-step).

#define Tt 256
#define Bb 64
#define Hh 1024
#define BH (Bb * Hh)

// Persistent state (device globals: the sanctioned scratch mechanism).
__device__ float g_h0[2][BH];  // layer 0 hidden, [parity][b*H]
__device__ float g_h1[2][BH];  // layer 1 hidden
__device__ float g_c[2][BH];   // cell state per layer (no double buffer needed)

__device__ __forceinline__ float sigmoidf_(float x) {
    return 1.0f / (1.0f + __expf(-x));
}

// One layer-step: gates = X @ Wih^T + Hin @ Whh^T + bih + bhh, then LSTM cell.
// Grid: 128 CTAs, each owns 8 hidden indices j (all 4 gates of each).
// Block: 128 threads; thread computes 4 batches x 4 gates of one j (16 accs,
// packed as 8 f32x2 pairs: (i,f) and (g,o) share the same activation a).
__global__ void __launch_bounds__(128, 1) lstm_step_kernel(
    const float* __restrict__ X,    // [B,H] input to this layer
    const float* __restrict__ Hin,  // [B,H] previous hidden of this layer
    const float* __restrict__ Wih,  // [4H,H]
    const float* __restrict__ Whh,  // [4H,H]
    const float* __restrict__ bih,  // [4H]
    const float* __restrict__ bhh,  // [4H]
    float* __restrict__ Hout,       // [B,H]
    float* __restrict__ C)          // [B,H] in/out
{
    __shared__ float As[64][33];    // [b][k] activation tile, pad 33: conflict-free
    __shared__ float Ws[32][34];    // [k][j2*4+g] weight tile, pad 34: 8B-aligned rows

    const int tid = threadIdx.x;
    const int j0  = blockIdx.x * 8;
    const int jj  = tid & 7;         // which j within CTA
    const int bq  = tid >> 3;        // 0..15
    const int b0  = bq * 4;          // batch group base
    const int kk  = tid & 31;        // loader lane
    const int r   = tid >> 5;        // loader row group 0..3
    const int j   = j0 + jj;

    // Seed accumulators with biases (added exactly once per (b,j)).
    float b_i = bih[j]          + bhh[j];
    float b_f = bih[1024 + j]   + bhh[1024 + j];
    float b_g = bih[2048 + j]   + bhh[2048 + j];
    float b_o = bih[3072 + j]   + bhh[3072 + j];
    unsigned long long bias01, bias23;
    asm("mov.b64 %0, {%1, %2};" : "=l"(bias01)
        : "r"(__float_as_uint(b_i)), "r"(__float_as_uint(b_f)));
    asm("mov.b64 %0, {%1, %2};" : "=l"(bias23)
        : "r"(__float_as_uint(b_g)), "r"(__float_as_uint(b_o)));

    unsigned long long acc01[4], acc23[4];
#pragma unroll
    for (int bi = 0; bi < 4; bi++) { acc01[bi] = bias01; acc23[bi] = bias23; }

    // Phase 0: A=X, W=Wih. Phase 1: A=Hin, W=Whh. K=1024 each, tiles of 32.
#pragma unroll 1
    for (int ph = 0; ph < 2; ph++) {
        const float* __restrict__ Ag = ph ? Hin : X;
        const float* __restrict__ Wg = ph ? Whh : Wih;
#pragma unroll 1
        for (int k0 = 0; k0 < 1024; k0 += 32) {
            __syncthreads();  // previous tile fully consumed
            // Load A tile [64 b][32 k]: coalesced over kk, conflict-free STS.
#pragma unroll
            for (int i = 0; i < 16; i++) {
                int b = r + i * 4;
                As[b][kk] = Ag[b * 1024 + k0 + kk];
            }
            // Load W tile: Ws[kk][j2*4+g] = W[(g*1024 + j0 + j2)*1024 + k0 + kk]
#pragma unroll
            for (int i = 0; i < 8; i++) {
                int nn = r + i * 4;        // 0..31
                int g  = nn & 3;
                int j2 = nn >> 2;
                Ws[kk][nn] = Wg[(g * 1024 + j0 + j2) * 1024 + k0 + kk];
            }
            __syncthreads();
#pragma unroll
            for (int k = 0; k < 32; k++) {
                // gates (i,f) pair and (g,o) pair for this j, at k
                unsigned long long w01 =
                    *(const unsigned long long*)&Ws[k][jj * 4];
                unsigned long long w23 =
                    *(const unsigned long long*)&Ws[k][jj * 4 + 2];
#pragma unroll
                for (int bi = 0; bi < 4; bi++) {
                    float a = As[b0 + bi][k];
                    unsigned long long a2;
                    asm("mov.b64 %0, {%1, %1};" : "=l"(a2)
                        : "r"(__float_as_uint(a)));
                    asm("fma.rn.f32x2 %0, %1, %2, %0;"
                        : "+l"(acc01[bi]) : "l"(a2), "l"(w01));
                    asm("fma.rn.f32x2 %0, %1, %2, %0;"
                        : "+l"(acc23[bi]) : "l"(a2), "l"(w23));
                }
            }
        }
    }

    // Fused LSTM cell update for the 4 (b, j) cells this thread owns.
#pragma unroll
    for (int bi = 0; bi < 4; bi++) {
        int b = b0 + bi;
        unsigned int ui, uf, ug, uo;
        asm("mov.b64 {%0, %1}, %2;" : "=r"(ui), "=r"(uf) : "l"(acc01[bi]));
        asm("mov.b64 {%0, %1}, %2;" : "=r"(ug), "=r"(uo) : "l"(acc23[bi]));
        float ig = sigmoidf_(__uint_as_float(ui));
        float fg = sigmoidf_(__uint_as_float(uf));
        float gt = tanhf(__uint_as_float(ug));
        float og = sigmoidf_(__uint_as_float(uo));
        float cn = fg * C[b * 1024 + j] + ig * gt;
        C[b * 1024 + j]    = cn;
        Hout[b * 1024 + j] = og * tanhf(cn);
    }
}

extern "C" void kernel_launch(void* const* d_in, const int* in_sizes, int n_in,
                              void* d_out, int out_size) {
    const float* x_seq = (const float*)d_in[0];  // [T,B,H]
    const float* h0    = (const float*)d_in[1];  // [L,B,H]
    const float* c0    = (const float*)d_in[2];  // [L,B,H]
    const float* Wih   = (const float*)d_in[3];  // [L,4H,H]
    const float* Whh   = (const float*)d_in[4];  // [L,4H,H]
    const float* bih   = (const float*)d_in[5];  // [L,4H]
    const float* bhh   = (const float*)d_in[6];  // [L,4H]

    float *gh0, *gh1, *gc;
    cudaGetSymbolAddress((void**)&gh0, g_h0);
    cudaGetSymbolAddress((void**)&gh1, g_h1);
    cudaGetSymbolAddress((void**)&gc,  g_c);

    const size_t bhBytes = (size_t)BH * sizeof(float);

    // Reinitialize state every call (deterministic; parity 0 holds t=0 input).
    cudaMemcpyAsync(gh0, h0,          bhBytes,     cudaMemcpyDeviceToDevice);
    cudaMemcpyAsync(gh1, h0 + BH,     bhBytes,     cudaMemcpyDeviceToDevice);
    cudaMemcpyAsync(gc,  c0,          2 * bhBytes, cudaMemcpyDeviceToDevice);

    const size_t Woff = (size_t)4096 * 1024;  // per-layer weight stride
    for (int t = 0; t < Tt; t++) {
        int p = t & 1;
        // Layer 0: x = input_seq[t]
        lstm_step_kernel<<<128, 128>>>(
            x_seq + (size_t)t * BH,
            gh0 + (size_t)p * BH,
            Wih, Whh, bih, bhh,
            gh0 + (size_t)(p ^ 1) * BH,
            gc);
        // Layer 1: x = layer-0 new hidden (stream-ordered after layer 0)
        lstm_step_kernel<<<128, 128>>>(
            gh0 + (size_t)(p ^ 1) * BH,
            gh1 + (size_t)p * BH,
            Wih + Woff, Whh + Woff, bih + 4096, bhh + 4096,
            gh1 + (size_t)(p ^ 1) * BH,
            gc + BH);
    }

    // Final hidden of top layer lives at parity (255&1)^1 = 0.
    cudaMemcpyAsync(d_out, gh1, bhBytes, cudaMemcpyDeviceToDevice);
}

// round 3
// speedup vs baseline: 3.1740x; 3.1740x over previous
#include <cuda_runtime.h>
#include <cuda_bf16.h>
#include <cstdint>

// StackLSTM T=256, B=64, H=1024, L=2 — Round 3.
// tcgen05 unavailable (harness PTX target is compute_103, no 'a' features).
// Use mma.sync bf16 (sm_80 baseline) with 3-term split precision:
//   gates = a_hi@Whi + a_hi@Wlo + a_lo@Whi   (fp32 accumulate)
// Whi chunk is loaded once and reused against both B_hi and B_lo.

#define Tt 256
#define Bb 64
#define Hh 1024
#define BH (Bb * Hh)                 // 65536
#define M4H 4096
#define KK 2048                      // K per layer-step (x 1024 | h 1024)
#define WPL (2ULL * M4H * KK)        // bf16 elems per layer (hi+lo)
#define STAGE 24576                  // A 8KB (hi+lo) + B 16KB (hi+lo)
#define SMEM_TOTAL (3 * STAGE)       // 73728

// ---------------- persistent device state ----------------
__device__ __nv_bfloat16 g_xhi[Tt * BH];
__device__ __nv_bfloat16 g_xlo[Tt * BH];
__device__ __nv_bfloat16 g_W[2 * WPL];     // [layer][hl][4096 perm rows][2048]
__device__ float         g_bsum[2 * M4H];
__device__ __nv_bfloat16 g_Hhi[2 * 2 * BH];  // [layer][parity][BH]
__device__ __nv_bfloat16 g_Hlo[2 * 2 * BH];
__device__ float         g_C[2 * BH];
__device__ float         g_Hf[2 * BH];

// ---------------- helpers ----------------
__device__ __forceinline__ uint32_t smem_u32(const void* p) {
    uint32_t a;
    asm("{ .reg .u64 t; cvta.to.shared.u64 t, %1; cvt.u32.u64 %0, t; }"
        : "=r"(a) : "l"(p));
    return a;
}
__device__ __forceinline__ void cp16(uint32_t d, const void* g) {
    asm volatile("cp.async.cg.shared.global [%0], [%1], 16;"
                 :: "r"(d), "l"(g) : "memory");
}
#define CP_COMMIT() asm volatile("cp.async.commit_group;" ::: "memory")

#define LDSM4(r, addr) \
    asm volatile("ldmatrix.sync.aligned.m8n8.x4.shared.b16 {%0,%1,%2,%3}, [%4];" \
        : "=r"((r)[0]), "=r"((r)[1]), "=r"((r)[2]), "=r"((r)[3]) : "r"(addr))

#define HMMA(d, a, b0, b1) \
    asm volatile("mma.sync.aligned.m16n8k16.row.col.f32.bf16.bf16.f32 " \
        "{%0,%1,%2,%3},{%4,%5,%6,%7},{%8,%9},{%0,%1,%2,%3};" \
        : "+f"((d)[0]), "+f"((d)[1]), "+f"((d)[2]), "+f"((d)[3]) \
        : "r"((a)[0]), "r"((a)[1]), "r"((a)[2]), "r"((a)[3]), "r"(b0), "r"(b1))

__device__ __forceinline__ float sigm(float x) { return 1.0f / (1.0f + __expf(-x)); }
__device__ __forceinline__ float tanh_(float x) {
    float ax = fabsf(x);
    float e  = __expf(-2.0f * ax);
    return copysignf((1.0f - e) / (1.0f + e), x);
}

// ---------------- prep kernels ----------------
__global__ void split_x_kernel(const float* __restrict__ x, int n) {
    for (int i = blockIdx.x * blockDim.x + threadIdx.x; i < n;
         i += gridDim.x * blockDim.x) {
        float v = x[i];
        __nv_bfloat16 hi = __float2bfloat16(v);
        g_xhi[i] = hi;
        g_xlo[i] = __float2bfloat16(v - __bfloat162float(hi));
    }
}

__global__ void init_state_kernel(const float* __restrict__ h0,
                                  const float* __restrict__ c0,
                                  const float* __restrict__ bih,
                                  const float* __restrict__ bhh) {
    int t0 = blockIdx.x * blockDim.x + threadIdx.x;
    for (int idx = t0; idx < 2 * BH; idx += gridDim.x * blockDim.x) {
        int l = idx / BH, r = idx % BH;
        float hv = h0[idx];
        __nv_bfloat16 hi = __float2bfloat16(hv);
        g_Hhi[(l * 2 + 0) * BH + r] = hi;
        g_Hlo[(l * 2 + 0) * BH + r] = __float2bfloat16(hv - __bfloat162float(hi));
        g_C[idx] = c0[idx];
    }
    for (int idx = t0; idx < 2 * M4H; idx += gridDim.x * blockDim.x)
        g_bsum[idx] = bih[idx] + bhh[idx];
}

// g_W[l][hl][p][k]: permuted row p: blk=p>>5, lcl=p&31, gate=lcl>>3, jl=lcl&7,
// j=blk*8+jl, source row = gate*1024+j. k<1024 -> Wih, else Whh.
__global__ void prep_w_kernel(const float* __restrict__ Wih,
                              const float* __restrict__ Whh) {
    const long long per = (long long)M4H * KK;          // 8388608
    const long long n   = 2 * 2 * per;
    for (long long idx = blockIdx.x * (long long)blockDim.x + threadIdx.x; idx < n;
         idx += (long long)gridDim.x * blockDim.x) {
        int  l  = (int)(idx / (2 * per));
        long long r1 = idx % (2 * per);
        int  hl = (int)(r1 / per);
        long long r2 = r1 % per;
        int  p  = (int)(r2 / KK), k = (int)(r2 % KK);
        int  blk = p >> 5, lcl = p & 31;
        int  gate = lcl >> 3, jl = lcl & 7;
        int  j = blk * 8 + jl;
        int  srow = gate * 1024 + j;
        float w = (k < 1024)
                ? Wih[(size_t)l * M4H * Hh + (size_t)srow * Hh + k]
                : Whh[(size_t)l * M4H * Hh + (size_t)srow * Hh + (k - 1024)];
        __nv_bfloat16 hi = __float2bfloat16(w);
        g_W[idx] = hl ? __float2bfloat16(w - __bfloat162float(hi)) : hi;
    }
}

// ---------------- main layer-step kernel ----------------
// grid = 128 CTAs (M=32 gate-rows each), block = 256 (8 warps, 2x4 M x N grid).
__global__ void __launch_bounds__(256, 1) lstm_step_mma(
    const __nv_bfloat16* __restrict__ W,     // this layer: [2][4096][2048]
    const float*         __restrict__ bsum,  // [4096]
    const __nv_bfloat16* __restrict__ xhi,   // [64][1024]
    const __nv_bfloat16* __restrict__ xlo,
    const __nv_bfloat16* __restrict__ hhi,
    const __nv_bfloat16* __restrict__ hlo,
    __nv_bfloat16* __restrict__ ohi,
    __nv_bfloat16* __restrict__ olo,
    float* __restrict__ C,
    float* __restrict__ Hf)
{
    extern __shared__ char smem[];
    const uint32_t sb  = smem_u32(smem);
    const int tid  = threadIdx.x;
    const int wid  = tid >> 5, lane = tid & 31;
    const int blk  = blockIdx.x;
    const int wm   = wid & 1;        // M16 tile
    const int wn   = wid >> 1;       // N16 tile (0..3)

    const int rowA = wm * 16 + (lane & 15);
    const int rowB = wn * 16 + (lane & 7) + ((lane >> 4) << 3);
    const uint32_t aRow = rowA * 128, aSw = (rowA & 7);
    const uint32_t bRow = rowB * 128, bSw = (rowB & 7);

    float d0[4] = {0.f, 0.f, 0.f, 0.f};
    float d1[4] = {0.f, 0.f, 0.f, 0.f};

    auto load_chunk = [&](int kc) {
        const int st = kc % 3;
        const uint32_t stA = sb + st * STAGE;
        const uint32_t stB = stA + 8192;
        const int k0 = kc * 64;
        // A: [2 hl][32 rows][8 q] 16B units = 512; 2/thread
#pragma unroll
        for (int i = 0; i < 2; i++) {
            int u = tid + i * 256;
            int hl = u >> 8, rem = u & 255, row = rem >> 3, q = rem & 7;
            const __nv_bfloat16* s = W + (size_t)hl * (M4H * KK)
                                   + (size_t)(blk * 32 + row) * KK + k0 + q * 8;
            cp16(stA + hl * 4096 + row * 128 + ((q ^ (row & 7)) << 4), s);
        }
        // B: [2 hl][64 rows][8 q] = 1024 units; 4/thread
        const __nv_bfloat16* bh_src;
        const __nv_bfloat16* bl_src;
        int koff;
        if (k0 < 1024) { bh_src = xhi; bl_src = xlo; koff = k0; }
        else           { bh_src = hhi; bl_src = hlo; koff = k0 - 1024; }
#pragma unroll
        for (int i = 0; i < 4; i++) {
            int u = tid + i * 256;
            int hl = u >> 9, rem = u & 511, row = rem >> 3, q = rem & 7;
            const __nv_bfloat16* s =
                (hl ? bl_src : bh_src) + (size_t)row * 1024 + koff + q * 8;
            cp16(stB + hl * 8192 + row * 128 + ((q ^ (row & 7)) << 4), s);
        }
        CP_COMMIT();
    };

    load_chunk(0);
    load_chunk(1);

    for (int c = 0; c < 32; ++c) {
        if (c < 30) asm volatile("cp.async.wait_group 1;" ::: "memory");
        else        asm volatile("cp.async.wait_group 0;" ::: "memory");
        __syncthreads();
        if (c + 2 < 32) load_chunk(c + 2);

        const uint32_t stA = sb + (c % 3) * STAGE;
        const uint32_t stB = stA + 8192;
#pragma unroll
        for (int kk = 0; kk < 4; kk++) {
            const uint32_t qa = 2 * kk + (lane >> 4);
            const uint32_t qb = 2 * kk + ((lane >> 3) & 1);
            const uint32_t aHi = stA + aRow + ((qa ^ aSw) << 4);
            const uint32_t bHi = stB + bRow + ((qb ^ bSw) << 4);
            uint32_t ah[4], al[4], bh[4], bl[4];
            LDSM4(ah, aHi);
            LDSM4(al, aHi + 4096);
            LDSM4(bh, bHi);
            LDSM4(bl, bHi + 8192);
            HMMA(d0, ah, bh[0], bh[1]);
            HMMA(d1, ah, bh[2], bh[3]);
            HMMA(d0, ah, bl[0], bl[1]);
            HMMA(d1, ah, bl[2], bl[3]);
            HMMA(d0, al, bh[0], bh[1]);
            HMMA(d1, al, bh[2], bh[3]);
        }
    }

    // ---------------- epilogue: fused LSTM cell ----------------
    __syncthreads();                      // all stages consumed; overlay gb
    float* gb = (float*)smem;             // [32][66]
    {
        const int m = wm * 16 + (lane >> 2);
        const int n = wn * 16 + 2 * (lane & 3);
        *(float2*)&gb[m * 66 + n]           = make_float2(d0[0], d0[1]);
        *(float2*)&gb[(m + 8) * 66 + n]     = make_float2(d0[2], d0[3]);
        *(float2*)&gb[m * 66 + n + 8]       = make_float2(d1[0], d1[1]);
        *(float2*)&gb[(m + 8) * 66 + n + 8] = make_float2(d1[2], d1[3]);
    }
    __syncthreads();

    const int jl = tid & 7;
    const int bb = tid >> 3;              // 0..31
    const int j  = blk * 8 + jl;
    const float bI = bsum[j],        bF = bsum[1024 + j];
    const float bG = bsum[2048 + j], bO = bsum[3072 + j];
#pragma unroll
    for (int half = 0; half < 2; half++) {
        const int b = bb + half * 32;
        float gi = gb[(0 * 8 + jl) * 66 + b] + bI;
        float gf = gb[(1 * 8 + jl) * 66 + b] + bF;
        float gg = gb[(2 * 8 + jl) * 66 + b] + bG;
        float go = gb[(3 * 8 + jl) * 66 + b] + bO;
        float cn = sigm(gf) * C[b * Hh + j] + sigm(gi) * tanh_(gg);
        C[b * Hh + j] = cn;
        float hn = sigm(go) * tanh_(cn);
        Hf[b * Hh + j] = hn;
        __nv_bfloat16 hi = __float2bfloat16(hn);
        ohi[b * Hh + j] = hi;
        olo[b * Hh + j] = __float2bfloat16(hn - __bfloat162float(hi));
    }
}

// ---------------- host launcher ----------------
extern "C" void kernel_launch(void* const* d_in, const int* in_sizes, int n_in,
                              void* d_out, int out_size) {
    const float* x_seq = (const float*)d_in[0];
    const float* h0    = (const float*)d_in[1];
    const float* c0    = (const float*)d_in[2];
    const float* Wih   = (const float*)d_in[3];
    const float* Whh   = (const float*)d_in[4];
    const float* bih   = (const float*)d_in[5];
    const float* bhh   = (const float*)d_in[6];

    cudaFuncSetAttribute(lstm_step_mma,
                         cudaFuncAttributeMaxDynamicSharedMemorySize, SMEM_TOTAL);

    void *p_xhi, *p_xlo, *p_w, *p_bs, *p_hhi, *p_hlo, *p_c, *p_hf;
    cudaGetSymbolAddress(&p_xhi, g_xhi);
    cudaGetSymbolAddress(&p_xlo, g_xlo);
    cudaGetSymbolAddress(&p_w,   g_W);
    cudaGetSymbolAddress(&p_bs,  g_bsum);
    cudaGetSymbolAddress(&p_hhi, g_Hhi);
    cudaGetSymbolAddress(&p_hlo, g_Hlo);
    cudaGetSymbolAddress(&p_c,   g_C);
    cudaGetSymbolAddress(&p_hf,  g_Hf);

    __nv_bfloat16* xhi = (__nv_bfloat16*)p_xhi;
    __nv_bfloat16* xlo = (__nv_bfloat16*)p_xlo;
    __nv_bfloat16* Wg  = (__nv_bfloat16*)p_w;
    float*         bs  = (float*)p_bs;
    __nv_bfloat16* Hhi = (__nv_bfloat16*)p_hhi;
    __nv_bfloat16* Hlo = (__nv_bfloat16*)p_hlo;
    float*         Cst = (float*)p_c;
    float*         Hf  = (float*)p_hf;

    split_x_kernel<<<8192, 256>>>(x_seq, Tt * BH);
    init_state_kernel<<<512, 256>>>(h0, c0, bih, bhh);
    prep_w_kernel<<<8192, 256>>>(Wih, Whh);

    for (int t = 0; t < Tt; t++) {
        const int p = t & 1;
        // layer 0
        lstm_step_mma<<<128, 256, SMEM_TOTAL>>>(
            Wg, bs,
            xhi + (size_t)t * BH, xlo + (size_t)t * BH,
            Hhi + (size_t)p * BH, Hlo + (size_t)p * BH,
            Hhi + (size_t)(p ^ 1) * BH, Hlo + (size_t)(p ^ 1) * BH,
            Cst, Hf);
        // layer 1 (input = layer 0's fresh hidden, already split)
        lstm_step_mma<<<128, 256, SMEM_TOTAL>>>(
            Wg + WPL, bs + M4H,
            Hhi + (size_t)(p ^ 1) * BH, Hlo + (size_t)(p ^ 1) * BH,
            Hhi + (size_t)(2 + p) * BH, Hlo + (size_t)(2 + p) * BH,
            Hhi + (size_t)(2 + (p ^ 1)) * BH, Hlo + (size_t)(2 + (p ^ 1)) * BH,
            Cst + BH, Hf + BH);
    }
    cudaMemcpyAsync(d_out, Hf + BH, (size_t)BH * sizeof(float),
                    cudaMemcpyDeviceToDevice);
}

// round 4
// speedup vs baseline: 4.0348x; 1.2712x over previous
#include <cuda_runtime.h>
#include <cuda_bf16.h>
#include <cstdint>

// StackLSTM T=256, B=64, H=1024, L=2 — Round 4.
// mma.sync bf16 3-term split (a_hi@Whi + a_hi@Wlo + a_lo@Whi), fp32 accum.
// R4 change: 512-thread CTAs, two independent 256-thread K-split groups
// (group0: x-half K, group1: h-half K), each with its own 3-stage cp.async
// pipeline and named barrier -> 2x warp parallelism to hide latency.

#define Tt 256
#define Bb 64
#define Hh 1024
#define BH (Bb * Hh)                 // 65536
#define M4H 4096
#define KK 2048
#define WPL (2ULL * M4H * KK)        // bf16 elems per layer (hi+lo)
#define STAGE 24576                  // A 8KB (hi+lo) + B 16KB (hi+lo)
#define GSZ (3 * STAGE)              // 73728 per group
#define SMEM_TOTAL (2 * GSZ)         // 147456

// ---------------- persistent device state ----------------
__device__ __nv_bfloat16 g_xhi[Tt * BH];
__device__ __nv_bfloat16 g_xlo[Tt * BH];
__device__ __nv_bfloat16 g_W[2 * WPL];       // [layer][hl][4096 perm rows][2048]
__device__ float         g_bsum[2 * M4H];
__device__ __nv_bfloat16 g_Hhi[2 * 2 * BH];  // [layer][parity][BH]
__device__ __nv_bfloat16 g_Hlo[2 * 2 * BH];
__device__ float         g_C[2 * BH];
__device__ float         g_Hf[2 * BH];

// ---------------- helpers ----------------
__device__ __forceinline__ uint32_t smem_u32(const void* p) {
    uint32_t a;
    asm("{ .reg .u64 t; cvta.to.shared.u64 t, %1; cvt.u32.u64 %0, t; }"
        : "=r"(a) : "l"(p));
    return a;
}
__device__ __forceinline__ void cp16(uint32_t d, const void* g) {
    asm volatile("cp.async.cg.shared.global [%0], [%1], 16;"
                 :: "r"(d), "l"(g) : "memory");
}
#define CP_COMMIT() asm volatile("cp.async.commit_group;" ::: "memory")

#define LDSM4(r, addr) \
    asm volatile("ldmatrix.sync.aligned.m8n8.x4.shared.b16 {%0,%1,%2,%3}, [%4];" \
        : "=r"((r)[0]), "=r"((r)[1]), "=r"((r)[2]), "=r"((r)[3]) : "r"(addr))

#define HMMA(d, a, b0, b1) \
    asm volatile("mma.sync.aligned.m16n8k16.row.col.f32.bf16.bf16.f32 " \
        "{%0,%1,%2,%3},{%4,%5,%6,%7},{%8,%9},{%0,%1,%2,%3};" \
        : "+f"((d)[0]), "+f"((d)[1]), "+f"((d)[2]), "+f"((d)[3]) \
        : "r"((a)[0]), "r"((a)[1]), "r"((a)[2]), "r"((a)[3]), "r"(b0), "r"(b1))

__device__ __forceinline__ void gbar(int grp) {
    if (grp == 0) asm volatile("bar.sync 1, 256;" ::: "memory");
    else          asm volatile("bar.sync 2, 256;" ::: "memory");
}

__device__ __forceinline__ float sigm(float x) { return 1.0f / (1.0f + __expf(-x)); }
__device__ __forceinline__ float tanh_(float x) {
    float ax = fabsf(x);
    float e  = __expf(-2.0f * ax);
    return copysignf((1.0f - e) / (1.0f + e), x);
}

// ---------------- prep kernels ----------------
__global__ void split_x_kernel(const float* __restrict__ x, int n) {
    for (int i = blockIdx.x * blockDim.x + threadIdx.x; i < n;
         i += gridDim.x * blockDim.x) {
        float v = x[i];
        __nv_bfloat16 hi = __float2bfloat16(v);
        g_xhi[i] = hi;
        g_xlo[i] = __float2bfloat16(v - __bfloat162float(hi));
    }
}

__global__ void init_state_kernel(const float* __restrict__ h0,
                                  const float* __restrict__ c0,
                                  const float* __restrict__ bih,
                                  const float* __restrict__ bhh) {
    int t0 = blockIdx.x * blockDim.x + threadIdx.x;
    for (int idx = t0; idx < 2 * BH; idx += gridDim.x * blockDim.x) {
        int l = idx / BH, r = idx % BH;
        float hv = h0[idx];
        __nv_bfloat16 hi = __float2bfloat16(hv);
        g_Hhi[(l * 2 + 0) * BH + r] = hi;
        g_Hlo[(l * 2 + 0) * BH + r] = __float2bfloat16(hv - __bfloat162float(hi));
        g_C[idx] = c0[idx];
    }
    for (int idx = t0; idx < 2 * M4H; idx += gridDim.x * blockDim.x)
        g_bsum[idx] = bih[idx] + bhh[idx];
}

// g_W[l][hl][p][k]: permuted row p: blk=p>>5, lcl=p&31, gate=lcl>>3, jl=lcl&7,
// j=blk*8+jl, source row = gate*1024+j. k<1024 -> Wih, else Whh.
__global__ void prep_w_kernel(const float* __restrict__ Wih,
                              const float* __restrict__ Whh) {
    const long long per = (long long)M4H * KK;
    const long long n   = 2 * 2 * per;
    for (long long idx = blockIdx.x * (long long)blockDim.x + threadIdx.x; idx < n;
         idx += (long long)gridDim.x * blockDim.x) {
        int  l  = (int)(idx / (2 * per));
        long long r1 = idx % (2 * per);
        int  hl = (int)(r1 / per);
        long long r2 = r1 % per;
        int  p  = (int)(r2 / KK), k = (int)(r2 % KK);
        int  blk = p >> 5, lcl = p & 31;
        int  gate = lcl >> 3, jl = lcl & 7;
        int  j = blk * 8 + jl;
        int  srow = gate * 1024 + j;
        float w = (k < 1024)
                ? Wih[(size_t)l * M4H * Hh + (size_t)srow * Hh + k]
                : Whh[(size_t)l * M4H * Hh + (size_t)srow * Hh + (k - 1024)];
        __nv_bfloat16 hi = __float2bfloat16(w);
        g_W[idx] = hl ? __float2bfloat16(w - __bfloat162float(hi)) : hi;
    }
}

// ---------------- main layer-step kernel ----------------
// grid = 128 CTAs (M=32 gate-rows), block = 512 (2 groups x 8 warps, 2Mx4N).
__global__ void __launch_bounds__(512, 1) lstm_step_mma(
    const __nv_bfloat16* __restrict__ W,     // this layer: [2][4096][2048]
    const float*         __restrict__ bsum,  // [4096]
    const __nv_bfloat16* __restrict__ xhi,   // [64][1024]
    const __nv_bfloat16* __restrict__ xlo,
    const __nv_bfloat16* __restrict__ hhi,
    const __nv_bfloat16* __restrict__ hlo,
    __nv_bfloat16* __restrict__ ohi,
    __nv_bfloat16* __restrict__ olo,
    float* __restrict__ C,
    float* __restrict__ Hf)
{
    extern __shared__ char smem[];
    const int tid  = threadIdx.x;
    const int grp  = tid >> 8;           // K-split group: 0 -> x half, 1 -> h half
    const int gtid = tid & 255;
    const int wid  = gtid >> 5, lane = tid & 31;
    const int blk  = blockIdx.x;
    const int wm   = wid & 1;            // M16 tile
    const int wn   = wid >> 1;           // N16 tile (0..3)
    const uint32_t sb = smem_u32(smem) + grp * GSZ;

    const int rowA = wm * 16 + (lane & 15);
    const int rowB = wn * 16 + (lane & 7) + ((lane >> 4) << 3);
    const uint32_t aRow = rowA * 128, aSw = (rowA & 7);
    const uint32_t bRow = rowB * 128, bSw = (rowB & 7);

    // group-specific activation sources (each group covers K 1024 = 16 chunks)
    const __nv_bfloat16* bh_src = grp ? hhi : xhi;
    const __nv_bfloat16* bl_src = grp ? hlo : xlo;
    const __nv_bfloat16* Wbase  = W + (size_t)(blk * 32) * KK + grp * 1024;

    float d0[4] = {0.f, 0.f, 0.f, 0.f};
    float d1[4] = {0.f, 0.f, 0.f, 0.f};

    auto load_chunk = [&](int lc) {
        const int st = lc % 3;
        const uint32_t stA = sb + st * STAGE;
        const uint32_t stB = stA + 8192;
        const int koff = lc * 64;
        // A: [2 hl][32 rows][8 q] = 512 16B units; 2/thread (256 thr)
#pragma unroll
        for (int i = 0; i < 2; i++) {
            int u = gtid + i * 256;
            int hl = u >> 8, rem = u & 255, row = rem >> 3, q = rem & 7;
            const __nv_bfloat16* s = Wbase + (size_t)hl * (M4H * KK)
                                   + (size_t)row * KK + koff + q * 8;
            cp16(stA + hl * 4096 + row * 128 + ((q ^ (row & 7)) << 4), s);
        }
        // B: [2 hl][64 rows][8 q] = 1024 units; 4/thread
#pragma unroll
        for (int i = 0; i < 4; i++) {
            int u = gtid + i * 256;
            int hl = u >> 9, rem = u & 511, row = rem >> 3, q = rem & 7;
            const __nv_bfloat16* s =
                (hl ? bl_src : bh_src) + (size_t)row * 1024 + koff + q * 8;
            cp16(stB + hl * 8192 + row * 128 + ((q ^ (row & 7)) << 4), s);
        }
        CP_COMMIT();
    };

    load_chunk(0);
    load_chunk(1);

    for (int lc = 0; lc < 16; ++lc) {
        if (lc < 14) asm volatile("cp.async.wait_group 1;" ::: "memory");
        else         asm volatile("cp.async.wait_group 0;" ::: "memory");
        gbar(grp);
        if (lc + 2 < 16) load_chunk(lc + 2);

        const uint32_t stA = sb + (lc % 3) * STAGE;
        const uint32_t stB = stA + 8192;
#pragma unroll
        for (int kk = 0; kk < 4; kk++) {
            const uint32_t qa = 2 * kk + (lane >> 4);
            const uint32_t qb = 2 * kk + ((lane >> 3) & 1);
            const uint32_t aHi = stA + aRow + ((qa ^ aSw) << 4);
            const uint32_t bHi = stB + bRow + ((qb ^ bSw) << 4);
            uint32_t ah[4], al[4], bh[4], bl[4];
            LDSM4(ah, aHi);
            LDSM4(al, aHi + 4096);
            LDSM4(bh, bHi);
            LDSM4(bl, bHi + 8192);
            HMMA(d0, ah, bh[0], bh[1]);
            HMMA(d1, ah, bh[2], bh[3]);
            HMMA(d0, ah, bl[0], bl[1]);
            HMMA(d1, ah, bl[2], bl[3]);
            HMMA(d0, al, bh[0], bh[1]);
            HMMA(d1, al, bh[2], bh[3]);
        }
        gbar(grp);   // all group warps done with stage before overwrite
    }

    // ---------------- epilogue: sum group partials, fused LSTM cell -------
    __syncthreads();                      // both groups done; overlay stages
    float* gb  = (float*)smem;            // [2][32][66]
    float* myb = gb + grp * (32 * 66);
    {
        const int m = wm * 16 + (lane >> 2);
        const int n = wn * 16 + 2 * (lane & 3);
        *(float2*)&myb[m * 66 + n]           = make_float2(d0[0], d0[1]);
        *(float2*)&myb[(m + 8) * 66 + n]     = make_float2(d0[2], d0[3]);
        *(float2*)&myb[m * 66 + n + 8]       = make_float2(d1[0], d1[1]);
        *(float2*)&myb[(m + 8) * 66 + n + 8] = make_float2(d1[2], d1[3]);
    }
    __syncthreads();

    // 512 threads cover all 8 j x 64 b cells in one pass.
    const int jl = tid & 7;
    const int b  = tid >> 3;              // 0..63
    const int j  = blk * 8 + jl;
    const float bI = bsum[j],        bF = bsum[1024 + j];
    const float bG = bsum[2048 + j], bO = bsum[3072 + j];
    float gi = gb[(0 * 8 + jl) * 66 + b] + gb[2112 + (0 * 8 + jl) * 66 + b] + bI;
    float gf = gb[(1 * 8 + jl) * 66 + b] + gb[2112 + (1 * 8 + jl) * 66 + b] + bF;
    float gg = gb[(2 * 8 + jl) * 66 + b] + gb[2112 + (2 * 8 + jl) * 66 + b] + bG;
    float go = gb[(3 * 8 + jl) * 66 + b] + gb[2112 + (3 * 8 + jl) * 66 + b] + bO;
    float cn = sigm(gf) * C[b * Hh + j] + sigm(gi) * tanh_(gg);
    C[b * Hh + j] = cn;
    float hn = sigm(go) * tanh_(cn);
    Hf[b * Hh + j] = hn;
    __nv_bfloat16 hi = __float2bfloat16(hn);
    ohi[b * Hh + j] = hi;
    olo[b * Hh + j] = __float2bfloat16(hn - __bfloat162float(hi));
}

// ---------------- host launcher ----------------
extern "C" void kernel_launch(void* const* d_in, const int* in_sizes, int n_in,
                              void* d_out, int out_size) {
    const float* x_seq = (const float*)d_in[0];
    const float* h0    = (const float*)d_in[1];
    const float* c0    = (const float*)d_in[2];
    const float* Wih   = (const float*)d_in[3];
    const float* Whh   = (const float*)d_in[4];
    const float* bih   = (const float*)d_in[5];
    const float* bhh   = (const float*)d_in[6];

    cudaFuncSetAttribute(lstm_step_mma,
                         cudaFuncAttributeMaxDynamicSharedMemorySize, SMEM_TOTAL);

    void *p_xhi, *p_xlo, *p_w, *p_bs, *p_hhi, *p_hlo, *p_c, *p_hf;
    cudaGetSymbolAddress(&p_xhi, g_xhi);
    cudaGetSymbolAddress(&p_xlo, g_xlo);
    cudaGetSymbolAddress(&p_w,   g_W);
    cudaGetSymbolAddress(&p_bs,  g_bsum);
    cudaGetSymbolAddress(&p_hhi, g_Hhi);
    cudaGetSymbolAddress(&p_hlo, g_Hlo);
    cudaGetSymbolAddress(&p_c,   g_C);
    cudaGetSymbolAddress(&p_hf,  g_Hf);

    __nv_bfloat16* xhi = (__nv_bfloat16*)p_xhi;
    __nv_bfloat16* xlo = (__nv_bfloat16*)p_xlo;
    __nv_bfloat16* Wg  = (__nv_bfloat16*)p_w;
    float*         bs  = (float*)p_bs;
    __nv_bfloat16* Hhi = (__nv_bfloat16*)p_hhi;
    __nv_bfloat16* Hlo = (__nv_bfloat16*)p_hlo;
    float*         Cst = (float*)p_c;
    float*         Hf  = (float*)p_hf;

    split_x_kernel<<<8192, 256>>>(x_seq, Tt * BH);
    init_state_kernel<<<512, 256>>>(h0, c0, bih, bhh);
    prep_w_kernel<<<8192, 256>>>(Wih, Whh);

    for (int t = 0; t < Tt; t++) {
        const int p = t & 1;
        // layer 0
        lstm_step_mma<<<128, 512, SMEM_TOTAL>>>(
            Wg, bs,
            xhi + (size_t)t * BH, xlo + (size_t)t * BH,
            Hhi + (size_t)p * BH, Hlo + (size_t)p * BH,
            Hhi + (size_t)(p ^ 1) * BH, Hlo + (size_t)(p ^ 1) * BH,
            Cst, Hf);
        // layer 1 (input = layer 0's fresh hidden, already split)
        lstm_step_mma<<<128, 512, SMEM_TOTAL>>>(
            Wg + WPL, bs + M4H,
            Hhi + (size_t)(p ^ 1) * BH, Hlo + (size_t)(p ^ 1) * BH,
            Hhi + (size_t)(2 + p) * BH, Hlo + (size_t)(2 + p) * BH,
            Hhi + (size_t)(2 + (p ^ 1)) * BH, Hlo + (size_t)(2 + (p ^ 1)) * BH,
            Cst + BH, Hf + BH);
    }
    cudaMemcpyAsync(d_out, Hf + BH, (size_t)BH * sizeof(float),
                    cudaMemcpyDeviceToDevice);
}

// round 5
// speedup vs baseline: 4.0388x; 1.0010x over previous
#include <cuda_runtime.h>
#include <cuda_bf16.h>
#include <cstdint>

// StackLSTM T=256, B=64, H=1024, L=2 — Round 5.
// mma.sync bf16 3-term split (a_hi@Whi + a_hi@Wlo + a_lo@Whi), fp32 accum.
// R5 changes vs R4: 4-stage cp.async pipeline (lookahead 3), single barrier
// per chunk, 6 independent HMMA accumulator chains (depth 12 -> 4).

#define Tt 256
#define Bb 64
#define Hh 1024
#define BH (Bb * Hh)                 // 65536
#define M4H 4096
#define KK 2048
#define WPL (2ULL * M4H * KK)        // bf16 elems per layer (hi+lo)
#define STAGE 24576                  // A 8KB (hi+lo) + B 16KB (hi+lo)
#define NSTAGE 4
#define GSZ (NSTAGE * STAGE)         // 98304 per group
#define SMEM_TOTAL (2 * GSZ)         // 196608

// ---------------- persistent device state ----------------
__device__ __nv_bfloat16 g_xhi[Tt * BH];
__device__ __nv_bfloat16 g_xlo[Tt * BH];
__device__ __nv_bfloat16 g_W[2 * WPL];       // [layer][hl][4096 perm rows][2048]
__device__ float         g_bsum[2 * M4H];
__device__ __nv_bfloat16 g_Hhi[2 * 2 * BH];  // [layer][parity][BH]
__device__ __nv_bfloat16 g_Hlo[2 * 2 * BH];
__device__ float         g_C[2 * BH];
__device__ float         g_Hf[2 * BH];

// ---------------- helpers ----------------
__device__ __forceinline__ uint32_t smem_u32(const void* p) {
    uint32_t a;
    asm("{ .reg .u64 t; cvta.to.shared.u64 t, %1; cvt.u32.u64 %0, t; }"
        : "=r"(a) : "l"(p));
    return a;
}
__device__ __forceinline__ void cp16(uint32_t d, const void* g) {
    asm volatile("cp.async.cg.shared.global [%0], [%1], 16;"
                 :: "r"(d), "l"(g) : "memory");
}
#define CP_COMMIT() asm volatile("cp.async.commit_group;" ::: "memory")

#define LDSM4(r, addr) \
    asm volatile("ldmatrix.sync.aligned.m8n8.x4.shared.b16 {%0,%1,%2,%3}, [%4];" \
        : "=r"((r)[0]), "=r"((r)[1]), "=r"((r)[2]), "=r"((r)[3]) : "r"(addr))

#define HMMA(d, a, b0, b1) \
    asm volatile("mma.sync.aligned.m16n8k16.row.col.f32.bf16.bf16.f32 " \
        "{%0,%1,%2,%3},{%4,%5,%6,%7},{%8,%9},{%0,%1,%2,%3};" \
        : "+f"((d)[0]), "+f"((d)[1]), "+f"((d)[2]), "+f"((d)[3]) \
        : "r"((a)[0]), "r"((a)[1]), "r"((a)[2]), "r"((a)[3]), "r"(b0), "r"(b1))

__device__ __forceinline__ void gbar(int grp) {
    if (grp == 0) asm volatile("bar.sync 1, 256;" ::: "memory");
    else          asm volatile("bar.sync 2, 256;" ::: "memory");
}

__device__ __forceinline__ float sigm(float x) { return 1.0f / (1.0f + __expf(-x)); }
__device__ __forceinline__ float tanh_(float x) {
    float ax = fabsf(x);
    float e  = __expf(-2.0f * ax);
    return copysignf((1.0f - e) / (1.0f + e), x);
}

// ---------------- prep kernels ----------------
__global__ void split_x_kernel(const float* __restrict__ x, int n) {
    for (int i = blockIdx.x * blockDim.x + threadIdx.x; i < n;
         i += gridDim.x * blockDim.x) {
        float v = x[i];
        __nv_bfloat16 hi = __float2bfloat16(v);
        g_xhi[i] = hi;
        g_xlo[i] = __float2bfloat16(v - __bfloat162float(hi));
    }
}

__global__ void init_state_kernel(const float* __restrict__ h0,
                                  const float* __restrict__ c0,
                                  const float* __restrict__ bih,
                                  const float* __restrict__ bhh) {
    int t0 = blockIdx.x * blockDim.x + threadIdx.x;
    for (int idx = t0; idx < 2 * BH; idx += gridDim.x * blockDim.x) {
        int l = idx / BH, r = idx % BH;
        float hv = h0[idx];
        __nv_bfloat16 hi = __float2bfloat16(hv);
        g_Hhi[(l * 2 + 0) * BH + r] = hi;
        g_Hlo[(l * 2 + 0) * BH + r] = __float2bfloat16(hv - __bfloat162float(hi));
        g_C[idx] = c0[idx];
    }
    for (int idx = t0; idx < 2 * M4H; idx += gridDim.x * blockDim.x)
        g_bsum[idx] = bih[idx] + bhh[idx];
}

// g_W[l][hl][p][k]: permuted row p: blk=p>>5, lcl=p&31, gate=lcl>>3, jl=lcl&7,
// j=blk*8+jl, source row = gate*1024+j. k<1024 -> Wih, else Whh.
__global__ void prep_w_kernel(const float* __restrict__ Wih,
                              const float* __restrict__ Whh) {
    const long long per = (long long)M4H * KK;
    const long long n   = 2 * 2 * per;
    for (long long idx = blockIdx.x * (long long)blockDim.x + threadIdx.x; idx < n;
         idx += (long long)gridDim.x * blockDim.x) {
        int  l  = (int)(idx / (2 * per));
        long long r1 = idx % (2 * per);
        int  hl = (int)(r1 / per);
        long long r2 = r1 % per;
        int  p  = (int)(r2 / KK), k = (int)(r2 % KK);
        int  blk = p >> 5, lcl = p & 31;
        int  gate = lcl >> 3, jl = lcl & 7;
        int  j = blk * 8 + jl;
        int  srow = gate * 1024 + j;
        float w = (k < 1024)
                ? Wih[(size_t)l * M4H * Hh + (size_t)srow * Hh + k]
                : Whh[(size_t)l * M4H * Hh + (size_t)srow * Hh + (k - 1024)];
        __nv_bfloat16 hi = __float2bfloat16(w);
        g_W[idx] = hl ? __float2bfloat16(w - __bfloat162float(hi)) : hi;
    }
}

// ---------------- main layer-step kernel ----------------
// grid = 128 CTAs (M=32 gate-rows), block = 512 (2 K-split groups x 8 warps).
__global__ void __launch_bounds__(512, 1) lstm_step_mma(
    const __nv_bfloat16* __restrict__ W,     // this layer: [2][4096][2048]
    const float*         __restrict__ bsum,  // [4096]
    const __nv_bfloat16* __restrict__ xhi,   // [64][1024]
    const __nv_bfloat16* __restrict__ xlo,
    const __nv_bfloat16* __restrict__ hhi,
    const __nv_bfloat16* __restrict__ hlo,
    __nv_bfloat16* __restrict__ ohi,
    __nv_bfloat16* __restrict__ olo,
    float* __restrict__ C,
    float* __restrict__ Hf)
{
    extern __shared__ char smem[];
    const int tid  = threadIdx.x;
    const int grp  = tid >> 8;           // K-split group: 0 -> x half, 1 -> h half
    const int gtid = tid & 255;
    const int wid  = gtid >> 5, lane = tid & 31;
    const int blk  = blockIdx.x;
    const int wm   = wid & 1;            // M16 tile
    const int wn   = wid >> 1;           // N16 tile (0..3)
    const uint32_t sb = smem_u32(smem) + grp * GSZ;

    const int rowA = wm * 16 + (lane & 15);
    const int rowB = wn * 16 + (lane & 7) + ((lane >> 4) << 3);
    const uint32_t aRow = rowA * 128, aSw = (rowA & 7);
    const uint32_t bRow = rowB * 128, bSw = (rowB & 7);

    // group-specific activation sources (each group covers K 1024 = 16 chunks)
    const __nv_bfloat16* bh_src = grp ? hhi : xhi;
    const __nv_bfloat16* bl_src = grp ? hlo : xlo;
    const __nv_bfloat16* Wbase  = W + (size_t)(blk * 32) * KK + grp * 1024;

    // 6 independent accumulator chains (hi-product + 2 corrections, x2 N-tiles)
    float d0h[4] = {0,0,0,0}, d0cA[4] = {0,0,0,0}, d0cB[4] = {0,0,0,0};
    float d1h[4] = {0,0,0,0}, d1cA[4] = {0,0,0,0}, d1cB[4] = {0,0,0,0};

    auto load_chunk = [&](int lc) {
        const int st = lc & 3;
        const uint32_t stA = sb + st * STAGE;
        const uint32_t stB = stA + 8192;
        const int koff = lc * 64;
        // A: [2 hl][32 rows][8 q] = 512 16B units; 2/thread (256 thr)
#pragma unroll
        for (int i = 0; i < 2; i++) {
            int u = gtid + i * 256;
            int hl = u >> 8, rem = u & 255, row = rem >> 3, q = rem & 7;
            const __nv_bfloat16* s = Wbase + (size_t)hl * (M4H * KK)
                                   + (size_t)row * KK + koff + q * 8;
            cp16(stA + hl * 4096 + row * 128 + ((q ^ (row & 7)) << 4), s);
        }
        // B: [2 hl][64 rows][8 q] = 1024 units; 4/thread
#pragma unroll
        for (int i = 0; i < 4; i++) {
            int u = gtid + i * 256;
            int hl = u >> 9, rem = u & 511, row = rem >> 3, q = rem & 7;
            const __nv_bfloat16* s =
                (hl ? bl_src : bh_src) + (size_t)row * 1024 + koff + q * 8;
            cp16(stB + hl * 8192 + row * 128 + ((q ^ (row & 7)) << 4), s);
        }
        CP_COMMIT();
    };

    load_chunk(0);
    load_chunk(1);
    load_chunk(2);

    for (int lc = 0; lc < 16; ++lc) {
        if (lc <= 13)      asm volatile("cp.async.wait_group 2;" ::: "memory");
        else if (lc == 14) asm volatile("cp.async.wait_group 1;" ::: "memory");
        else               asm volatile("cp.async.wait_group 0;" ::: "memory");
        gbar(grp);  // all group warps done with stage (lc-1) -> safe to overwrite
        if (lc + 3 < 16) load_chunk(lc + 3);

        const uint32_t stA = sb + (lc & 3) * STAGE;
        const uint32_t stB = stA + 8192;
#pragma unroll
        for (int kk = 0; kk < 4; kk++) {
            const uint32_t qa = 2 * kk + (lane >> 4);
            const uint32_t qb = 2 * kk + ((lane >> 3) & 1);
            const uint32_t aHi = stA + aRow + ((qa ^ aSw) << 4);
            const uint32_t bHi = stB + bRow + ((qb ^ bSw) << 4);
            uint32_t ah[4], al[4], bh[4], bl[4];
            LDSM4(ah, aHi);
            LDSM4(al, aHi + 4096);
            LDSM4(bh, bHi);
            LDSM4(bl, bHi + 8192);
            HMMA(d0h,  ah, bh[0], bh[1]);
            HMMA(d1h,  ah, bh[2], bh[3]);
            HMMA(d0cA, ah, bl[0], bl[1]);
            HMMA(d1cA, ah, bl[2], bl[3]);
            HMMA(d0cB, al, bh[0], bh[1]);
            HMMA(d1cB, al, bh[2], bh[3]);
        }
    }

    // ---------------- epilogue: sum group partials, fused LSTM cell -------
    float d0[4], d1[4];
#pragma unroll
    for (int i = 0; i < 4; i++) {
        d0[i] = d0h[i] + (d0cA[i] + d0cB[i]);
        d1[i] = d1h[i] + (d1cA[i] + d1cB[i]);
    }
    __syncthreads();                      // both groups done; overlay stages
    float* gb  = (float*)smem;            // [2][32][66]
    float* myb = gb + grp * (32 * 66);
    {
        const int m = wm * 16 + (lane >> 2);
        const int n = wn * 16 + 2 * (lane & 3);
        *(float2*)&myb[m * 66 + n]           = make_float2(d0[0], d0[1]);
        *(float2*)&myb[(m + 8) * 66 + n]     = make_float2(d0[2], d0[3]);
        *(float2*)&myb[m * 66 + n + 8]       = make_float2(d1[0], d1[1]);
        *(float2*)&myb[(m + 8) * 66 + n + 8] = make_float2(d1[2], d1[3]);
    }
    __syncthreads();

    // 512 threads cover all 8 j x 64 b cells in one pass.
    const int jl = tid & 7;
    const int b  = tid >> 3;              // 0..63
    const int j  = blk * 8 + jl;
    const float bI = bsum[j],        bF = bsum[1024 + j];
    const float bG = bsum[2048 + j], bO = bsum[3072 + j];
    float gi = gb[(0 * 8 + jl) * 66 + b] + gb[2112 + (0 * 8 + jl) * 66 + b] + bI;
    float gf = gb[(1 * 8 + jl) * 66 + b] + gb[2112 + (1 * 8 + jl) * 66 + b] + bF;
    float gg = gb[(2 * 8 + jl) * 66 + b] + gb[2112 + (2 * 8 + jl) * 66 + b] + bG;
    float go = gb[(3 * 8 + jl) * 66 + b] + gb[2112 + (3 * 8 + jl) * 66 + b] + bO;
    float cn = sigm(gf) * C[b * Hh + j] + sigm(gi) * tanh_(gg);
    C[b * Hh + j] = cn;
    float hn = sigm(go) * tanh_(cn);
    Hf[b * Hh + j] = hn;
    __nv_bfloat16 hi = __float2bfloat16(hn);
    ohi[b * Hh + j] = hi;
    olo[b * Hh + j] = __float2bfloat16(hn - __bfloat162float(hi));
}

// ---------------- host launcher ----------------
extern "C" void kernel_launch(void* const* d_in, const int* in_sizes, int n_in,
                              void* d_out, int out_size) {
    const float* x_seq = (const float*)d_in[0];
    const float* h0    = (const float*)d_in[1];
    const float* c0    = (const float*)d_in[2];
    const float* Wih   = (const float*)d_in[3];
    const float* Whh   = (const float*)d_in[4];
    const float* bih   = (const float*)d_in[5];
    const float* bhh   = (const float*)d_in[6];

    cudaFuncSetAttribute(lstm_step_mma,
                         cudaFuncAttributeMaxDynamicSharedMemorySize, SMEM_TOTAL);

    void *p_xhi, *p_xlo, *p_w, *p_bs, *p_hhi, *p_hlo, *p_c, *p_hf;
    cudaGetSymbolAddress(&p_xhi, g_xhi);
    cudaGetSymbolAddress(&p_xlo, g_xlo);
    cudaGetSymbolAddress(&p_w,   g_W);
    cudaGetSymbolAddress(&p_bs,  g_bsum);
    cudaGetSymbolAddress(&p_hhi, g_Hhi);
    cudaGetSymbolAddress(&p_hlo, g_Hlo);
    cudaGetSymbolAddress(&p_c,   g_C);
    cudaGetSymbolAddress(&p_hf,  g_Hf);

    __nv_bfloat16* xhi = (__nv_bfloat16*)p_xhi;
    __nv_bfloat16* xlo = (__nv_bfloat16*)p_xlo;
    __nv_bfloat16* Wg  = (__nv_bfloat16*)p_w;
    float*         bs  = (float*)p_bs;
    __nv_bfloat16* Hhi = (__nv_bfloat16*)p_hhi;
    __nv_bfloat16* Hlo = (__nv_bfloat16*)p_hlo;
    float*         Cst = (float*)p_c;
    float*         Hf  = (float*)p_hf;

    split_x_kernel<<<8192, 256>>>(x_seq, Tt * BH);
    init_state_kernel<<<512, 256>>>(h0, c0, bih, bhh);
    prep_w_kernel<<<8192, 256>>>(Wih, Whh);

    for (int t = 0; t < Tt; t++) {
        const int p = t & 1;
        // layer 0
        lstm_step_mma<<<128, 512, SMEM_TOTAL>>>(
            Wg, bs,
            xhi + (size_t)t * BH, xlo + (size_t)t * BH,
            Hhi + (size_t)p * BH, Hlo + (size_t)p * BH,
            Hhi + (size_t)(p ^ 1) * BH, Hlo + (size_t)(p ^ 1) * BH,
            Cst, Hf);
        // layer 1 (input = layer 0's fresh hidden, already split)
        lstm_step_mma<<<128, 512, SMEM_TOTAL>>>(
            Wg + WPL, bs + M4H,
            Hhi + (size_t)(p ^ 1) * BH, Hlo + (size_t)(p ^ 1) * BH,
            Hhi + (size_t)(2 + p) * BH, Hlo + (size_t)(2 + p) * BH,
            Hhi + (size_t)(2 + (p ^ 1)) * BH, Hlo + (size_t)(2 + (p ^ 1)) * BH,
            Cst + BH, Hf + BH);
    }
    cudaMemcpyAsync(d_out, Hf + BH, (size_t)BH * sizeof(float),
                    cudaMemcpyDeviceToDevice);
}

// round 6
// speedup vs baseline: 4.4088x; 1.0916x over previous
#include <cuda_runtime.h>
#include <cuda_bf16.h>
#include <cstdint>

// StackLSTM T=256, B=64, H=1024, L=2 — Round 6.
// mma.sync bf16 3-term split (a_hi@Whi + a_hi@Wlo + a_lo@Whi), fp32 accum.
// R6 change vs R5: warp tile M16xN16 -> M32xN32 with per-warp k16 ownership
// (sub = wid>>1) -> smem LDSM read traffic halved (64KB -> 32KB per chunk
// per group). L1/shared crossbar was the measured bottleneck (45.7%).

#define Tt 256
#define Bb 64
#define Hh 1024
#define BH (Bb * Hh)                 // 65536
#define M4H 4096
#define KK 2048
#define WPL (2ULL * M4H * KK)        // bf16 elems per layer (hi+lo)
#define STAGE 24576                  // A 8KB (hi+lo) + B 16KB (hi+lo)
#define NSTAGE 4
#define GSZ (NSTAGE * STAGE)         // 98304 per group
#define SMEM_TOTAL (2 * GSZ)         // 196608

// ---------------- persistent device state ----------------
__device__ __nv_bfloat16 g_xhi[Tt * BH];
__device__ __nv_bfloat16 g_xlo[Tt * BH];
__device__ __nv_bfloat16 g_W[2 * WPL];       // [layer][hl][4096 perm rows][2048]
__device__ float         g_bsum[2 * M4H];
__device__ __nv_bfloat16 g_Hhi[2 * 2 * BH];  // [layer][parity][BH]
__device__ __nv_bfloat16 g_Hlo[2 * 2 * BH];
__device__ float         g_C[2 * BH];
__device__ float         g_Hf[2 * BH];

// ---------------- helpers ----------------
__device__ __forceinline__ uint32_t smem_u32(const void* p) {
    uint32_t a;
    asm("{ .reg .u64 t; cvta.to.shared.u64 t, %1; cvt.u32.u64 %0, t; }"
        : "=r"(a) : "l"(p));
    return a;
}
__device__ __forceinline__ void cp16(uint32_t d, const void* g) {
    asm volatile("cp.async.cg.shared.global [%0], [%1], 16;"
                 :: "r"(d), "l"(g) : "memory");
}
#define CP_COMMIT() asm volatile("cp.async.commit_group;" ::: "memory")

#define LDSM4(r, addr) \
    asm volatile("ldmatrix.sync.aligned.m8n8.x4.shared.b16 {%0,%1,%2,%3}, [%4];" \
        : "=r"((r)[0]), "=r"((r)[1]), "=r"((r)[2]), "=r"((r)[3]) : "r"(addr))

#define HMMA(d, a0, a1, a2, a3, b0, b1) \
    asm volatile("mma.sync.aligned.m16n8k16.row.col.f32.bf16.bf16.f32 " \
        "{%0,%1,%2,%3},{%4,%5,%6,%7},{%8,%9},{%0,%1,%2,%3};" \
        : "+f"((d)[0]), "+f"((d)[1]), "+f"((d)[2]), "+f"((d)[3]) \
        : "r"(a0), "r"(a1), "r"(a2), "r"(a3), "r"(b0), "r"(b1))

__device__ __forceinline__ void gbar(int grp) {
    if (grp == 0) asm volatile("bar.sync 1, 256;" ::: "memory");
    else          asm volatile("bar.sync 2, 256;" ::: "memory");
}

__device__ __forceinline__ float sigm(float x) { return 1.0f / (1.0f + __expf(-x)); }
__device__ __forceinline__ float tanh_(float x) {
    float ax = fabsf(x);
    float e  = __expf(-2.0f * ax);
    return copysignf((1.0f - e) / (1.0f + e), x);
}

// ---------------- prep kernels ----------------
__global__ void split_x_kernel(const float* __restrict__ x, int n) {
    for (int i = blockIdx.x * blockDim.x + threadIdx.x; i < n;
         i += gridDim.x * blockDim.x) {
        float v = x[i];
        __nv_bfloat16 hi = __float2bfloat16(v);
        g_xhi[i] = hi;
        g_xlo[i] = __float2bfloat16(v - __bfloat162float(hi));
    }
}

__global__ void init_state_kernel(const float* __restrict__ h0,
                                  const float* __restrict__ c0,
                                  const float* __restrict__ bih,
                                  const float* __restrict__ bhh) {
    int t0 = blockIdx.x * blockDim.x + threadIdx.x;
    for (int idx = t0; idx < 2 * BH; idx += gridDim.x * blockDim.x) {
        int l = idx / BH, r = idx % BH;
        float hv = h0[idx];
        __nv_bfloat16 hi = __float2bfloat16(hv);
        g_Hhi[(l * 2 + 0) * BH + r] = hi;
        g_Hlo[(l * 2 + 0) * BH + r] = __float2bfloat16(hv - __bfloat162float(hi));
        g_C[idx] = c0[idx];
    }
    for (int idx = t0; idx < 2 * M4H; idx += gridDim.x * blockDim.x)
        g_bsum[idx] = bih[idx] + bhh[idx];
}

// g_W[l][hl][p][k]: permuted row p: blk=p>>5, lcl=p&31, gate=lcl>>3, jl=lcl&7,
// j=blk*8+jl, source row = gate*1024+j. k<1024 -> Wih, else Whh.
__global__ void prep_w_kernel(const float* __restrict__ Wih,
                              const float* __restrict__ Whh) {
    const long long per = (long long)M4H * KK;
    const long long n   = 2 * 2 * per;
    for (long long idx = blockIdx.x * (long long)blockDim.x + threadIdx.x; idx < n;
         idx += (long long)gridDim.x * blockDim.x) {
        int  l  = (int)(idx / (2 * per));
        long long r1 = idx % (2 * per);
        int  hl = (int)(r1 / per);
        long long r2 = r1 % per;
        int  p  = (int)(r2 / KK), k = (int)(r2 % KK);
        int  blk = p >> 5, lcl = p & 31;
        int  gate = lcl >> 3, jl = lcl & 7;
        int  j = blk * 8 + jl;
        int  srow = gate * 1024 + j;
        float w = (k < 1024)
                ? Wih[(size_t)l * M4H * Hh + (size_t)srow * Hh + k]
                : Whh[(size_t)l * M4H * Hh + (size_t)srow * Hh + (k - 1024)];
        __nv_bfloat16 hi = __float2bfloat16(w);
        g_W[idx] = hl ? __float2bfloat16(w - __bfloat162float(hi)) : hi;
    }
}

// ---------------- main layer-step kernel ----------------
// grid = 128 CTAs (M=32 gate-rows), block = 512 (2 K-split groups x 8 warps).
// Within a group: warp w -> sub=w>>1 owns k16 #sub of each K64 chunk,
// half=w&1 owns N32 half; warp tile = M32 x N32.
__global__ void __launch_bounds__(512, 1) lstm_step_mma(
    const __nv_bfloat16* __restrict__ W,     // this layer: [2][4096][2048]
    const float*         __restrict__ bsum,  // [4096]
    const __nv_bfloat16* __restrict__ xhi,   // [64][1024]
    const __nv_bfloat16* __restrict__ xlo,
    const __nv_bfloat16* __restrict__ hhi,
    const __nv_bfloat16* __restrict__ hlo,
    __nv_bfloat16* __restrict__ ohi,
    __nv_bfloat16* __restrict__ olo,
    float* __restrict__ C,
    float* __restrict__ Hf)
{
    extern __shared__ char smem[];
    const int tid  = threadIdx.x;
    const int grp  = tid >> 8;           // K-split group: 0 -> x half, 1 -> h half
    const int gtid = tid & 255;
    const int gwid = gtid >> 5, lane = tid & 31;
    const int blk  = blockIdx.x;
    const int sub  = gwid >> 1;          // k16 index within K64 chunk (0..3)
    const int half = gwid & 1;           // N32 half (0..1)
    const uint32_t sb = smem_u32(smem) + grp * GSZ;

    // fragment addressing (swizzled smem, 128B rows)
    const int rA  = lane & 15;                               // A row within m16
    const int rB  = (lane & 7) + ((lane >> 4) << 3);         // B row within n16
    const uint32_t qa = 2 * sub + (lane >> 4);               // A 16B-unit col
    const uint32_t qb = 2 * sub + ((lane >> 3) & 1);         // B 16B-unit col
    const uint32_t aOff = rA * 128 + (((qa ^ (rA & 7))) << 4);
    const uint32_t bOff = (half * 32 + rB) * 128 + (((qb ^ (rB & 7))) << 4);

    // group-specific sources (each group covers K 1024 = 16 chunks of K64)
    const __nv_bfloat16* bh_src = grp ? hhi : xhi;
    const __nv_bfloat16* bl_src = grp ? hlo : xlo;
    const __nv_bfloat16* Wbase  = W + (size_t)(blk * 32) * KK + grp * 1024;

    // M32xN32 accumulator: [mt][nt][u(n8)] x 4 regs
    float acc[8][4];
#pragma unroll
    for (int i = 0; i < 8; i++)
#pragma unroll
        for (int r = 0; r < 4; r++) acc[i][r] = 0.f;

    auto load_chunk = [&](int lc) {
        const int st = lc & 3;
        const uint32_t stA = sb + st * STAGE;
        const uint32_t stB = stA + 8192;
        const int koff = lc * 64;
        // A: [2 hl][32 rows][8 q] = 512 16B units; 2/thread (256 thr)
#pragma unroll
        for (int i = 0; i < 2; i++) {
            int u = gtid + i * 256;
            int hl = u >> 8, rem = u & 255, row = rem >> 3, q = rem & 7;
            const __nv_bfloat16* s = Wbase + (size_t)hl * (M4H * KK)
                                   + (size_t)row * KK + koff + q * 8;
            cp16(stA + hl * 4096 + row * 128 + ((q ^ (row & 7)) << 4), s);
        }
        // B: [2 hl][64 rows][8 q] = 1024 units; 4/thread
#pragma unroll
        for (int i = 0; i < 4; i++) {
            int u = gtid + i * 256;
            int hl = u >> 9, rem = u & 511, row = rem >> 3, q = rem & 7;
            const __nv_bfloat16* s =
                (hl ? bl_src : bh_src) + (size_t)row * 1024 + koff + q * 8;
            cp16(stB + hl * 8192 + row * 128 + ((q ^ (row & 7)) << 4), s);
        }
        CP_COMMIT();
    };

    load_chunk(0);
    load_chunk(1);
    load_chunk(2);

    for (int lc = 0; lc < 16; ++lc) {
        if (lc <= 13)      asm volatile("cp.async.wait_group 2;" ::: "memory");
        else if (lc == 14) asm volatile("cp.async.wait_group 1;" ::: "memory");
        else               asm volatile("cp.async.wait_group 0;" ::: "memory");
        gbar(grp);  // all group warps done with stage (lc-1) -> safe to overwrite
        if (lc + 3 < 16) load_chunk(lc + 3);

        const uint32_t stA = sb + (lc & 3) * STAGE;
        const uint32_t stB = stA + 8192;

        // 8 LDSM.x4: A m-tiles {0,16} hi/lo, B n-tiles {0,16} hi/lo
        uint32_t ah0[4], ah1[4], al0[4], al1[4];
        uint32_t bh0[4], bh1[4], bl0[4], bl1[4];
        LDSM4(ah0, stA + aOff);
        LDSM4(ah1, stA + aOff + 2048);          // +16 rows
        LDSM4(al0, stA + aOff + 4096);          // lo plane
        LDSM4(al1, stA + aOff + 4096 + 2048);
        LDSM4(bh0, stB + bOff);
        LDSM4(bh1, stB + bOff + 2048);          // +16 rows (n-tile 1)
        LDSM4(bl0, stB + bOff + 8192);          // lo plane
        LDSM4(bl1, stB + bOff + 8192 + 2048);

        // 24 HMMA: 3 terms x 2 mt x 2 nt x 2 n8, all into one accumulator set
#pragma unroll
        for (int t = 0; t < 3; t++) {
            const uint32_t* a0 = (t == 2) ? al0 : ah0;
            const uint32_t* a1 = (t == 2) ? al1 : ah1;
            const uint32_t* b0 = (t == 1) ? bl0 : bh0;
            const uint32_t* b1 = (t == 1) ? bl1 : bh1;
            HMMA(acc[0], a0[0], a0[1], a0[2], a0[3], b0[0], b0[1]);
            HMMA(acc[1], a0[0], a0[1], a0[2], a0[3], b0[2], b0[3]);
            HMMA(acc[2], a0[0], a0[1], a0[2], a0[3], b1[0], b1[1]);
            HMMA(acc[3], a0[0], a0[1], a0[2], a0[3], b1[2], b1[3]);
            HMMA(acc[4], a1[0], a1[1], a1[2], a1[3], b0[0], b0[1]);
            HMMA(acc[5], a1[0], a1[1], a1[2], a1[3], b0[2], b0[3]);
            HMMA(acc[6], a1[0], a1[1], a1[2], a1[3], b1[0], b1[1]);
            HMMA(acc[7], a1[0], a1[1], a1[2], a1[3], b1[2], b1[3]);
        }
    }

    // ---------------- epilogue: 8 partials -> fused LSTM cell -------------
    __syncthreads();                      // both groups done; overlay stages
    float* gb = (float*)smem;             // [8 partial][32 m][66]
    {
        float* myb = gb + (grp * 4 + sub) * (32 * 66);
        const int mrow = lane >> 2;
        const int ncol = 2 * (lane & 3);
#pragma unroll
        for (int i = 0; i < 8; i++) {
            const int mt = i >> 2, nt = (i >> 1) & 1, u = i & 1;
            const int m = mt * 16 + mrow;
            const int n = half * 32 + nt * 16 + u * 8 + ncol;
            *(float2*)&myb[m * 66 + n]       = make_float2(acc[i][0], acc[i][1]);
            *(float2*)&myb[(m + 8) * 66 + n] = make_float2(acc[i][2], acc[i][3]);
        }
    }
    __syncthreads();

    // 512 threads cover all 8 j x 64 b cells; each sums 8 partials per gate.
    const int jl = tid & 7;
    const int b  = tid >> 3;              // 0..63
    const int j  = blk * 8 + jl;
    float gsum[4];
#pragma unroll
    for (int g = 0; g < 4; g++) {
        float s = 0.f;
#pragma unroll
        for (int p = 0; p < 8; p++)
            s += gb[(p * 32 + g * 8 + jl) * 66 + b];
        gsum[g] = s;
    }
    float gi = gsum[0] + bsum[j];
    float gf = gsum[1] + bsum[1024 + j];
    float gg = gsum[2] + bsum[2048 + j];
    float go = gsum[3] + bsum[3072 + j];
    float cn = sigm(gf) * C[b * Hh + j] + sigm(gi) * tanh_(gg);
    C[b * Hh + j] = cn;
    float hn = sigm(go) * tanh_(cn);
    Hf[b * Hh + j] = hn;
    __nv_bfloat16 hi = __float2bfloat16(hn);
    ohi[b * Hh + j] = hi;
    olo[b * Hh + j] = __float2bfloat16(hn - __bfloat162float(hi));
}

// ---------------- host launcher ----------------
extern "C" void kernel_launch(void* const* d_in, const int* in_sizes, int n_in,
                              void* d_out, int out_size) {
    const float* x_seq = (const float*)d_in[0];
    const float* h0    = (const float*)d_in[1];
    const float* c0    = (const float*)d_in[2];
    const float* Wih   = (const float*)d_in[3];
    const float* Whh   = (const float*)d_in[4];
    const float* bih   = (const float*)d_in[5];
    const float* bhh   = (const float*)d_in[6];

    cudaFuncSetAttribute(lstm_step_mma,
                         cudaFuncAttributeMaxDynamicSharedMemorySize, SMEM_TOTAL);

    void *p_xhi, *p_xlo, *p_w, *p_bs, *p_hhi, *p_hlo, *p_c, *p_hf;
    cudaGetSymbolAddress(&p_xhi, g_xhi);
    cudaGetSymbolAddress(&p_xlo, g_xlo);
    cudaGetSymbolAddress(&p_w,   g_W);
    cudaGetSymbolAddress(&p_bs,  g_bsum);
    cudaGetSymbolAddress(&p_hhi, g_Hhi);
    cudaGetSymbolAddress(&p_hlo, g_Hlo);
    cudaGetSymbolAddress(&p_c,   g_C);
    cudaGetSymbolAddress(&p_hf,  g_Hf);

    __nv_bfloat16* xhi = (__nv_bfloat16*)p_xhi;
    __nv_bfloat16* xlo = (__nv_bfloat16*)p_xlo;
    __nv_bfloat16* Wg  = (__nv_bfloat16*)p_w;
    float*         bs  = (float*)p_bs;
    __nv_bfloat16* Hhi = (__nv_bfloat16*)p_hhi;
    __nv_bfloat16* Hlo = (__nv_bfloat16*)p_hlo;
    float*         Cst = (float*)p_c;
    float*         Hf  = (float*)p_hf;

    split_x_kernel<<<8192, 256>>>(x_seq, Tt * BH);
    init_state_kernel<<<512, 256>>>(h0, c0, bih, bhh);
    prep_w_kernel<<<8192, 256>>>(Wih, Whh);

    for (int t = 0; t < Tt; t++) {
        const int p = t & 1;
        // layer 0
        lstm_step_mma<<<128, 512, SMEM_TOTAL>>>(
            Wg, bs,
            xhi + (size_t)t * BH, xlo + (size_t)t * BH,
            Hhi + (size_t)p * BH, Hlo + (size_t)p * BH,
            Hhi + (size_t)(p ^ 1) * BH, Hlo + (size_t)(p ^ 1) * BH,
            Cst, Hf);
        // layer 1 (input = layer 0's fresh hidden, already split)
        lstm_step_mma<<<128, 512, SMEM_TOTAL>>>(
            Wg + WPL, bs + M4H,
            Hhi + (size_t)(p ^ 1) * BH, Hlo + (size_t)(p ^ 1) * BH,
            Hhi + (size_t)(2 + p) * BH, Hlo + (size_t)(2 + p) * BH,
            Hhi + (size_t)(2 + (p ^ 1)) * BH, Hlo + (size_t)(2 + (p ^ 1)) * BH,
            Cst + BH, Hf + BH);
    }
    cudaMemcpyAsync(d_out, Hf + BH, (size_t)BH * sizeof(float),
                    cudaMemcpyDeviceToDevice);
}